// round 1
// baseline (speedup 1.0000x reference)
#include <cuda_runtime.h>
#include <cuda_bf16.h>
#include <math.h>

// ---------------------------------------------------------------------------
// GPT-2 small forward: L=6, C=768, H=12, D=64, B=4, T=1024, V=32000
// Output layout: logits [4096*32000] | loss [1] | x_final [4096*768]
// ---------------------------------------------------------------------------

#define BT   4096       // B*T rows
#define CH   768        // channels
#define NH   12         // heads
#define DH   64         // head dim
#define TSEQ 1024       // sequence length
#define VOC  32000      // vocab
#define NLAY 6

// Scratch (device globals: no allocation allowed)
__device__ float g_x[BT * CH];
__device__ float g_h[BT * CH];
__device__ float g_qkv[BT * 3 * CH];
__device__ float g_y[BT * CH];
__device__ float g_m[BT * 4 * CH];
__device__ float g_num;
__device__ float g_den;

// ---------------------------------------------------------------------------
__global__ void embed_k(const int* __restrict__ idx, const float* __restrict__ wte,
                        const float* __restrict__ wpe, float* __restrict__ x) {
    int row = blockIdx.x;
    int t = row & (TSEQ - 1);
    int tok = idx[row];
    const float* a = wte + (size_t)tok * CH;
    const float* b = wpe + (size_t)t * CH;
    float* o = x + (size_t)row * CH;
    for (int c = threadIdx.x; c < CH; c += blockDim.x) o[c] = a[c] + b[c];
}

// ---------------------------------------------------------------------------
__global__ void ln_k(const float* __restrict__ x, const float* __restrict__ g,
                     const float* __restrict__ b, float* __restrict__ o) {
    __shared__ float r1[256], r2[256];
    int row = blockIdx.x;
    const float* xr = x + (size_t)row * CH;
    float s = 0.f, s2 = 0.f;
    for (int i = threadIdx.x; i < CH; i += 256) { float v = xr[i]; s += v; s2 += v * v; }
    r1[threadIdx.x] = s; r2[threadIdx.x] = s2;
    __syncthreads();
    for (int off = 128; off > 0; off >>= 1) {
        if (threadIdx.x < off) {
            r1[threadIdx.x] += r1[threadIdx.x + off];
            r2[threadIdx.x] += r2[threadIdx.x + off];
        }
        __syncthreads();
    }
    float mean = r1[0] * (1.0f / CH);
    float var  = r2[0] * (1.0f / CH) - mean * mean;
    float rstd = rsqrtf(var + 1e-5f);
    float* orow = o + (size_t)row * CH;
    for (int i = threadIdx.x; i < CH; i += 256)
        orow[i] = (xr[i] - mean) * rstd * g[i] + b[i];
}

// ---------------------------------------------------------------------------
// Tiled fp32 GEMM: C[M,N] = act(A[M,K] @ B[K,N] + bias) (+ residual)
// Tile 64x64x16, 256 threads, 4x4 per thread. M,N %64==0, K %16==0.
// ACT: 0=none, 1=exact GELU.  RES: 0=none, 1=add res (same shape as C).
template <int ACT, int RES>
__global__ void gemm_nn_k(const float* __restrict__ A, const float* __restrict__ B,
                          const float* __restrict__ bias, const float* __restrict__ res,
                          float* __restrict__ Cmat, int M, int N, int K) {
    __shared__ float As[16][65];
    __shared__ float Bs[16][64];
    int tx = threadIdx.x, ty = threadIdx.y;
    int tid = ty * 16 + tx;
    int row0 = blockIdx.y * 64, col0 = blockIdx.x * 64;
    float acc[4][4] = {};
    for (int k0 = 0; k0 < K; k0 += 16) {
#pragma unroll
        for (int i = tid; i < 1024; i += 256) {
            int m = i >> 4, kk = i & 15;
            As[kk][m] = A[(size_t)(row0 + m) * K + k0 + kk];
        }
#pragma unroll
        for (int i = tid; i < 1024; i += 256) {
            int kk = i >> 6, n = i & 63;
            Bs[kk][n] = B[(size_t)(k0 + kk) * N + col0 + n];
        }
        __syncthreads();
#pragma unroll
        for (int kk = 0; kk < 16; kk++) {
            float a0 = As[kk][ty * 4 + 0];
            float a1 = As[kk][ty * 4 + 1];
            float a2 = As[kk][ty * 4 + 2];
            float a3 = As[kk][ty * 4 + 3];
            float4 bb = *reinterpret_cast<const float4*>(&Bs[kk][tx * 4]);
            acc[0][0] += a0 * bb.x; acc[0][1] += a0 * bb.y; acc[0][2] += a0 * bb.z; acc[0][3] += a0 * bb.w;
            acc[1][0] += a1 * bb.x; acc[1][1] += a1 * bb.y; acc[1][2] += a1 * bb.z; acc[1][3] += a1 * bb.w;
            acc[2][0] += a2 * bb.x; acc[2][1] += a2 * bb.y; acc[2][2] += a2 * bb.z; acc[2][3] += a2 * bb.w;
            acc[3][0] += a3 * bb.x; acc[3][1] += a3 * bb.y; acc[3][2] += a3 * bb.z; acc[3][3] += a3 * bb.w;
        }
        __syncthreads();
    }
#pragma unroll
    for (int i = 0; i < 4; i++) {
        int r = row0 + ty * 4 + i;
#pragma unroll
        for (int j = 0; j < 4; j++) {
            int c = col0 + tx * 4 + j;
            float v = acc[i][j] + bias[c];
            if (ACT == 1) v = 0.5f * v * (1.0f + erff(v * 0.70710678118654752440f));
            if (RES == 1) v += res[(size_t)r * N + c];
            Cmat[(size_t)r * N + c] = v;
        }
    }
}

// ---------------------------------------------------------------------------
// NT GEMM: C[M,N] = A[M,K] @ W[N,K]^T  (tied lm head, no bias)
__global__ void gemm_nt_k(const float* __restrict__ A, const float* __restrict__ W,
                          float* __restrict__ Cmat, int M, int N, int K) {
    __shared__ float As[16][65];
    __shared__ float Bs[16][65];
    int tx = threadIdx.x, ty = threadIdx.y;
    int tid = ty * 16 + tx;
    int row0 = blockIdx.y * 64, col0 = blockIdx.x * 64;
    float acc[4][4] = {};
    for (int k0 = 0; k0 < K; k0 += 16) {
#pragma unroll
        for (int i = tid; i < 1024; i += 256) {
            int m = i >> 4, kk = i & 15;
            As[kk][m] = A[(size_t)(row0 + m) * K + k0 + kk];
        }
#pragma unroll
        for (int i = tid; i < 1024; i += 256) {
            int n = i >> 4, kk = i & 15;
            Bs[kk][n] = W[(size_t)(col0 + n) * K + k0 + kk];
        }
        __syncthreads();
#pragma unroll
        for (int kk = 0; kk < 16; kk++) {
            float a0 = As[kk][ty * 4 + 0];
            float a1 = As[kk][ty * 4 + 1];
            float a2 = As[kk][ty * 4 + 2];
            float a3 = As[kk][ty * 4 + 3];
            float b0 = Bs[kk][tx * 4 + 0];
            float b1 = Bs[kk][tx * 4 + 1];
            float b2 = Bs[kk][tx * 4 + 2];
            float b3 = Bs[kk][tx * 4 + 3];
            acc[0][0] += a0 * b0; acc[0][1] += a0 * b1; acc[0][2] += a0 * b2; acc[0][3] += a0 * b3;
            acc[1][0] += a1 * b0; acc[1][1] += a1 * b1; acc[1][2] += a1 * b2; acc[1][3] += a1 * b3;
            acc[2][0] += a2 * b0; acc[2][1] += a2 * b1; acc[2][2] += a2 * b2; acc[2][3] += a2 * b3;
            acc[3][0] += a3 * b0; acc[3][1] += a3 * b1; acc[3][2] += a3 * b2; acc[3][3] += a3 * b3;
        }
        __syncthreads();
    }
#pragma unroll
    for (int i = 0; i < 4; i++) {
        int r = row0 + ty * 4 + i;
#pragma unroll
        for (int j = 0; j < 4; j++) {
            int c = col0 + tx * 4 + j;
            Cmat[(size_t)r * N + c] = acc[i][j];
        }
    }
}

// ---------------------------------------------------------------------------
// Causal attention, one block per (t, h, b). Two phases:
//  A) 128 threads compute scores q.k_s into smem, softmax over s<=t
//  B) 64 threads (one per head dim) accumulate y_d = sum_s p_s * v[s,d]
__global__ void attn_k(const float* __restrict__ qkv, float* __restrict__ y) {
    __shared__ float qs[DH];
    __shared__ float sc[TSEQ];
    __shared__ float red[128];
    int t = blockIdx.x, h = blockIdx.y, b = blockIdx.z;
    int tid = threadIdx.x;
    const float* base = qkv + (size_t)b * TSEQ * (3 * CH);
    if (tid < DH) qs[tid] = base[(size_t)t * (3 * CH) + h * DH + tid];
    __syncthreads();
    int nS = t + 1;
    float lmax = -3.0e38f;
    for (int s = tid; s < nS; s += 128) {
        const float* kr = base + (size_t)s * (3 * CH) + CH + h * DH;
        float d = 0.f;
#pragma unroll
        for (int i = 0; i < DH; i++) d += qs[i] * kr[i];
        d *= 0.125f;  // 1/sqrt(64)
        sc[s] = d;
        lmax = fmaxf(lmax, d);
    }
    red[tid] = lmax;
    __syncthreads();
    for (int off = 64; off > 0; off >>= 1) {
        if (tid < off) red[tid] = fmaxf(red[tid], red[tid + off]);
        __syncthreads();
    }
    float mx = red[0];
    __syncthreads();
    float lsum = 0.f;
    for (int s = tid; s < nS; s += 128) {
        float e = __expf(sc[s] - mx);
        sc[s] = e;
        lsum += e;
    }
    red[tid] = lsum;
    __syncthreads();
    for (int off = 64; off > 0; off >>= 1) {
        if (tid < off) red[tid] += red[tid + off];
        __syncthreads();
    }
    float inv = 1.0f / red[0];
    __syncthreads();
    if (tid < DH) {
        const float* vr = base + 2 * CH + h * DH + tid;
        float acc = 0.f;
        for (int s = 0; s < nS; s++) acc += sc[s] * vr[(size_t)s * (3 * CH)];
        y[((size_t)(b * TSEQ + t)) * CH + h * DH + tid] = acc * inv;
    }
}

// ---------------------------------------------------------------------------
__global__ void zero_loss_k(float* num, float* den) { *num = 0.f; *den = 0.f; }

__global__ void loss_k(const float* __restrict__ logits, const int* __restrict__ tg,
                       float* num, float* den) {
    __shared__ float red[256];
    int row = blockIdx.x;
    const float* lr = logits + (size_t)row * VOC;
    float m = -3.0e38f;
    for (int j = threadIdx.x; j < VOC; j += 256) m = fmaxf(m, lr[j]);
    red[threadIdx.x] = m;
    __syncthreads();
    for (int off = 128; off > 0; off >>= 1) {
        if (threadIdx.x < off) red[threadIdx.x] = fmaxf(red[threadIdx.x], red[threadIdx.x + off]);
        __syncthreads();
    }
    m = red[0];
    __syncthreads();
    float s = 0.f;
    for (int j = threadIdx.x; j < VOC; j += 256) s += __expf(lr[j] - m);
    red[threadIdx.x] = s;
    __syncthreads();
    for (int off = 128; off > 0; off >>= 1) {
        if (threadIdx.x < off) red[threadIdx.x] += red[threadIdx.x + off];
        __syncthreads();
    }
    if (threadIdx.x == 0) {
        int t = tg[row];
        if (t != 0) {
            float lse = m + logf(red[0]);
            float nll = lse - lr[t];
            atomicAdd(num, nll);
            atomicAdd(den, 1.0f);
        }
    }
}

__global__ void final_loss_k(const float* num, const float* den, float* out) {
    out[0] = *num / fmaxf(*den, 1.0f);
}

// ---------------------------------------------------------------------------
extern "C" void kernel_launch(void* const* d_in, const int* in_sizes, int n_in,
                              void* d_out, int out_size) {
    const int*   idx     = (const int*)d_in[0];
    const int*   targets = (const int*)d_in[1];
    const float* wte     = (const float*)d_in[2];
    const float* wpe     = (const float*)d_in[3];
    const float* ln1_g   = (const float*)d_in[4];
    const float* ln1_b   = (const float*)d_in[5];
    const float* attn_w  = (const float*)d_in[6];
    const float* attn_b  = (const float*)d_in[7];
    const float* proj_w  = (const float*)d_in[8];
    const float* proj_b  = (const float*)d_in[9];
    const float* ln2_g   = (const float*)d_in[10];
    const float* ln2_b   = (const float*)d_in[11];
    const float* fc_w    = (const float*)d_in[12];
    const float* fc_b    = (const float*)d_in[13];
    const float* fc2_w   = (const float*)d_in[14];
    const float* fc2_b   = (const float*)d_in[15];
    const float* lnf_g   = (const float*)d_in[16];
    const float* lnf_b   = (const float*)d_in[17];
    float* out = (float*)d_out;

    float *x, *h, *qkv, *y, *mbuf, *pnum, *pden;
    cudaGetSymbolAddress((void**)&x, g_x);
    cudaGetSymbolAddress((void**)&h, g_h);
    cudaGetSymbolAddress((void**)&qkv, g_qkv);
    cudaGetSymbolAddress((void**)&y, g_y);
    cudaGetSymbolAddress((void**)&mbuf, g_m);
    cudaGetSymbolAddress((void**)&pnum, g_num);
    cudaGetSymbolAddress((void**)&pden, g_den);

    const size_t LOGN = (size_t)BT * VOC;
    float* out_loss = out + LOGN;
    float* out_x    = out + LOGN + 1;

    dim3 blk(16, 16);

    embed_k<<<BT, 256>>>(idx, wte, wpe, x);

    for (int l = 0; l < NLAY; l++) {
        ln_k<<<BT, 256>>>(x, ln1_g + l * CH, ln1_b + l * CH, h);
        gemm_nn_k<0, 0><<<dim3(3 * CH / 64, BT / 64), blk>>>(
            h, attn_w + (size_t)l * CH * 3 * CH, attn_b + (size_t)l * 3 * CH,
            nullptr, qkv, BT, 3 * CH, CH);
        attn_k<<<dim3(TSEQ, NH, 4), 128>>>(qkv, y);
        gemm_nn_k<0, 1><<<dim3(CH / 64, BT / 64), blk>>>(
            y, proj_w + (size_t)l * CH * CH, proj_b + (size_t)l * CH,
            x, x, BT, CH, CH);
        ln_k<<<BT, 256>>>(x, ln2_g + l * CH, ln2_b + l * CH, h);
        gemm_nn_k<1, 0><<<dim3(4 * CH / 64, BT / 64), blk>>>(
            h, fc_w + (size_t)l * CH * 4 * CH, fc_b + (size_t)l * 4 * CH,
            nullptr, mbuf, BT, 4 * CH, CH);
        gemm_nn_k<0, 1><<<dim3(CH / 64, BT / 64), blk>>>(
            mbuf, fc2_w + (size_t)l * 4 * CH * CH, fc2_b + (size_t)l * CH,
            x, x, BT, CH, 4 * CH);
    }

    ln_k<<<BT, 256>>>(x, lnf_g, lnf_b, out_x);
    gemm_nt_k<<<dim3(VOC / 64, BT / 64), blk>>>(out_x, wte, out, BT, VOC, CH);
    zero_loss_k<<<1, 1>>>(pnum, pden);
    loss_k<<<BT, 256>>>(out, targets, pnum, pden);
    final_loss_k<<<1, 1>>>(pnum, pden, out_loss);
}

// round 3
// speedup vs baseline: 1.1398x; 1.1398x over previous
#include <cuda_runtime.h>
#include <cuda_bf16.h>
#include <math.h>

// ---------------------------------------------------------------------------
// GPT-2 small forward: L=6, C=768, H=12, D=64, B=4, T=1024, V=32000
// Output layout: logits [4096*32000] | loss [1] | x_final [4096*768]
// Round 3: FFMA2 GEMMs (128x128 tiles); fix misaligned lm-head A loads by
// routing final LN through aligned scratch and copying to the +1-offset output.
// ---------------------------------------------------------------------------

#define BT   4096
#define CH   768
#define NH   12
#define DH   64
#define TSEQ 1024
#define VOC  32000
#define NLAY 6

typedef unsigned long long ull;

// Scratch (device globals: no allocation allowed)
__device__ float g_x[BT * CH];
__device__ float g_h[BT * CH];
__device__ float g_qkv[BT * 3 * CH];
__device__ float g_y[BT * CH];
__device__ float g_m[BT * 4 * CH];
__device__ float g_num;
__device__ float g_den;

// ---------------------------------------------------------------------------
__global__ void embed_k(const int* __restrict__ idx, const float* __restrict__ wte,
                        const float* __restrict__ wpe, float* __restrict__ x) {
    int row = blockIdx.x;
    int t = row & (TSEQ - 1);
    int tok = idx[row];
    const float* a = wte + (size_t)tok * CH;
    const float* b = wpe + (size_t)t * CH;
    float* o = x + (size_t)row * CH;
    for (int c = threadIdx.x; c < CH; c += blockDim.x) o[c] = a[c] + b[c];
}

__global__ void copy_k(const float* __restrict__ src, float* __restrict__ dst, int n) {
    int i = blockIdx.x * blockDim.x + threadIdx.x;
    if (i < n) dst[i] = src[i];
}

// ---------------------------------------------------------------------------
__global__ void ln_k(const float* __restrict__ x, const float* __restrict__ g,
                     const float* __restrict__ b, float* __restrict__ o) {
    __shared__ float r1[256], r2[256];
    int row = blockIdx.x;
    const float* xr = x + (size_t)row * CH;
    float s = 0.f, s2 = 0.f;
    for (int i = threadIdx.x; i < CH; i += 256) { float v = xr[i]; s += v; s2 += v * v; }
    r1[threadIdx.x] = s; r2[threadIdx.x] = s2;
    __syncthreads();
    for (int off = 128; off > 0; off >>= 1) {
        if (threadIdx.x < off) {
            r1[threadIdx.x] += r1[threadIdx.x + off];
            r2[threadIdx.x] += r2[threadIdx.x + off];
        }
        __syncthreads();
    }
    float mean = r1[0] * (1.0f / CH);
    float var  = r2[0] * (1.0f / CH) - mean * mean;
    float rstd = rsqrtf(var + 1e-5f);
    float* orow = o + (size_t)row * CH;
    for (int i = threadIdx.x; i < CH; i += 256)
        orow[i] = (xr[i] - mean) * rstd * g[i] + b[i];
}

// ---------------------------------------------------------------------------
// FFMA2 helpers
__device__ __forceinline__ ull pack_dup(float a) {
    ull r;
    asm("mov.b64 %0, {%1, %1};" : "=l"(r) : "f"(a));
    return r;
}
__device__ __forceinline__ void ffma2(ull& acc, ull a, ull b) {
    asm("fma.rn.f32x2 %0, %1, %2, %0;" : "+l"(acc) : "l"(a), "l"(b));
}
__device__ __forceinline__ float lo32(ull v) { return __uint_as_float((unsigned)v); }
__device__ __forceinline__ float hi32(ull v) { return __uint_as_float((unsigned)(v >> 32)); }

// ---------------------------------------------------------------------------
// Tiled fp32 GEMM (FFMA2): C[M,N] = act(A[M,K] @ B[K,N] + bias) (+ residual)
// Tile 128x128x16, 256 threads, 8x8 per thread (32 f32x2 accumulators).
// A must be 16B-aligned with K%16==0; M,N %128==0.
template <int ACT, int RES>
__global__ __launch_bounds__(256, 2)
void gemm_nn_k(const float* __restrict__ A, const float* __restrict__ B,
               const float* __restrict__ bias, const float* __restrict__ res,
               float* __restrict__ Cmat, int M, int N, int K) {
    __shared__ __align__(16) float As[16][132];
    __shared__ __align__(16) float Bs[16][132];
    int tid = threadIdx.x;
    int tx = tid & 15, ty = tid >> 4;
    int row0 = blockIdx.y * 128, col0 = blockIdx.x * 128;
    ull acc[8][4] = {};
    const float* Ab = A + (size_t)row0 * K;

    for (int k0 = 0; k0 < K; k0 += 16) {
#pragma unroll
        for (int i = 0; i < 2; i++) {
            int li = tid + i * 256;
            int m = li >> 2, kq = li & 3;
            float4 v = *reinterpret_cast<const float4*>(&Ab[(size_t)m * K + k0 + kq * 4]);
            As[kq * 4 + 0][m] = v.x;
            As[kq * 4 + 1][m] = v.y;
            As[kq * 4 + 2][m] = v.z;
            As[kq * 4 + 3][m] = v.w;
        }
#pragma unroll
        for (int i = 0; i < 2; i++) {
            int li = tid + i * 256;
            int kk = li >> 5, nq = li & 31;
            float4 v = *reinterpret_cast<const float4*>(&B[(size_t)(k0 + kk) * N + col0 + nq * 4]);
            *reinterpret_cast<float4*>(&Bs[kk][nq * 4]) = v;
        }
        __syncthreads();
#pragma unroll
        for (int kk = 0; kk < 16; kk++) {
            float4 a0 = *reinterpret_cast<const float4*>(&As[kk][ty * 8]);
            float4 a1 = *reinterpret_cast<const float4*>(&As[kk][ty * 8 + 4]);
            ull ap[8];
            ap[0] = pack_dup(a0.x); ap[1] = pack_dup(a0.y);
            ap[2] = pack_dup(a0.z); ap[3] = pack_dup(a0.w);
            ap[4] = pack_dup(a1.x); ap[5] = pack_dup(a1.y);
            ap[6] = pack_dup(a1.z); ap[7] = pack_dup(a1.w);
            const ull* bq = reinterpret_cast<const ull*>(&Bs[kk][tx * 8]);
            ull bp0 = bq[0], bp1 = bq[1], bp2 = bq[2], bp3 = bq[3];
#pragma unroll
            for (int i = 0; i < 8; i++) {
                ffma2(acc[i][0], ap[i], bp0);
                ffma2(acc[i][1], ap[i], bp1);
                ffma2(acc[i][2], ap[i], bp2);
                ffma2(acc[i][3], ap[i], bp3);
            }
        }
        __syncthreads();
    }
#pragma unroll
    for (int i = 0; i < 8; i++) {
        int r = row0 + ty * 8 + i;
#pragma unroll
        for (int j = 0; j < 4; j++) {
            int c = col0 + tx * 8 + j * 2;
            float v0 = lo32(acc[i][j]) + bias[c];
            float v1 = hi32(acc[i][j]) + bias[c + 1];
            if (ACT == 1) {
                v0 = 0.5f * v0 * (1.0f + erff(v0 * 0.70710678118654752440f));
                v1 = 0.5f * v1 * (1.0f + erff(v1 * 0.70710678118654752440f));
            }
            if (RES == 1) {
                float2 rv = *reinterpret_cast<const float2*>(&res[(size_t)r * N + c]);
                v0 += rv.x; v1 += rv.y;
            }
            float2 ov = make_float2(v0, v1);
            *reinterpret_cast<float2*>(&Cmat[(size_t)r * N + c]) = ov;
        }
    }
}

// ---------------------------------------------------------------------------
// NT GEMM (FFMA2): C[M,N] = A[M,K] @ W[N,K]^T  (tied lm head, no bias)
__global__ __launch_bounds__(256, 2)
void gemm_nt_k(const float* __restrict__ A, const float* __restrict__ W,
               float* __restrict__ Cmat, int M, int N, int K) {
    __shared__ __align__(16) float As[16][132];
    __shared__ __align__(16) float Bs[16][132];
    int tid = threadIdx.x;
    int tx = tid & 15, ty = tid >> 4;
    int row0 = blockIdx.y * 128, col0 = blockIdx.x * 128;
    ull acc[8][4] = {};
    const float* Ab = A + (size_t)row0 * K;
    const float* Wb = W + (size_t)col0 * K;

    for (int k0 = 0; k0 < K; k0 += 16) {
#pragma unroll
        for (int i = 0; i < 2; i++) {
            int li = tid + i * 256;
            int m = li >> 2, kq = li & 3;
            float4 v = *reinterpret_cast<const float4*>(&Ab[(size_t)m * K + k0 + kq * 4]);
            As[kq * 4 + 0][m] = v.x;
            As[kq * 4 + 1][m] = v.y;
            As[kq * 4 + 2][m] = v.z;
            As[kq * 4 + 3][m] = v.w;
        }
#pragma unroll
        for (int i = 0; i < 2; i++) {
            int li = tid + i * 256;
            int n = li >> 2, kq = li & 3;
            float4 v = *reinterpret_cast<const float4*>(&Wb[(size_t)n * K + k0 + kq * 4]);
            Bs[kq * 4 + 0][n] = v.x;
            Bs[kq * 4 + 1][n] = v.y;
            Bs[kq * 4 + 2][n] = v.z;
            Bs[kq * 4 + 3][n] = v.w;
        }
        __syncthreads();
#pragma unroll
        for (int kk = 0; kk < 16; kk++) {
            float4 a0 = *reinterpret_cast<const float4*>(&As[kk][ty * 8]);
            float4 a1 = *reinterpret_cast<const float4*>(&As[kk][ty * 8 + 4]);
            ull ap[8];
            ap[0] = pack_dup(a0.x); ap[1] = pack_dup(a0.y);
            ap[2] = pack_dup(a0.z); ap[3] = pack_dup(a0.w);
            ap[4] = pack_dup(a1.x); ap[5] = pack_dup(a1.y);
            ap[6] = pack_dup(a1.z); ap[7] = pack_dup(a1.w);
            const ull* bq = reinterpret_cast<const ull*>(&Bs[kk][tx * 8]);
            ull bp0 = bq[0], bp1 = bq[1], bp2 = bq[2], bp3 = bq[3];
#pragma unroll
            for (int i = 0; i < 8; i++) {
                ffma2(acc[i][0], ap[i], bp0);
                ffma2(acc[i][1], ap[i], bp1);
                ffma2(acc[i][2], ap[i], bp2);
                ffma2(acc[i][3], ap[i], bp3);
            }
        }
        __syncthreads();
    }
#pragma unroll
    for (int i = 0; i < 8; i++) {
        int r = row0 + ty * 8 + i;
#pragma unroll
        for (int j = 0; j < 4; j++) {
            int c = col0 + tx * 8 + j * 2;
            float2 ov = make_float2(lo32(acc[i][j]), hi32(acc[i][j]));
            *reinterpret_cast<float2*>(&Cmat[(size_t)r * N + c]) = ov;
        }
    }
}

// ---------------------------------------------------------------------------
// Causal attention, one block per (t, h, b).
__global__ void attn_k(const float* __restrict__ qkv, float* __restrict__ y) {
    __shared__ float qs[DH];
    __shared__ float sc[TSEQ];
    __shared__ float red[128];
    int t = blockIdx.x, h = blockIdx.y, b = blockIdx.z;
    int tid = threadIdx.x;
    const float* base = qkv + (size_t)b * TSEQ * (3 * CH);
    if (tid < DH) qs[tid] = base[(size_t)t * (3 * CH) + h * DH + tid];
    __syncthreads();
    int nS = t + 1;
    float lmax = -3.0e38f;
    for (int s = tid; s < nS; s += 128) {
        const float* kr = base + (size_t)s * (3 * CH) + CH + h * DH;
        float d = 0.f;
#pragma unroll
        for (int i = 0; i < DH; i++) d += qs[i] * kr[i];
        d *= 0.125f;
        sc[s] = d;
        lmax = fmaxf(lmax, d);
    }
    red[tid] = lmax;
    __syncthreads();
    for (int off = 64; off > 0; off >>= 1) {
        if (tid < off) red[tid] = fmaxf(red[tid], red[tid + off]);
        __syncthreads();
    }
    float mx = red[0];
    __syncthreads();
    float lsum = 0.f;
    for (int s = tid; s < nS; s += 128) {
        float e = __expf(sc[s] - mx);
        sc[s] = e;
        lsum += e;
    }
    red[tid] = lsum;
    __syncthreads();
    for (int off = 64; off > 0; off >>= 1) {
        if (tid < off) red[tid] += red[tid + off];
        __syncthreads();
    }
    float inv = 1.0f / red[0];
    __syncthreads();
    if (tid < DH) {
        const float* vr = base + 2 * CH + h * DH + tid;
        float acc = 0.f;
        for (int s = 0; s < nS; s++) acc += sc[s] * vr[(size_t)s * (3 * CH)];
        y[((size_t)(b * TSEQ + t)) * CH + h * DH + tid] = acc * inv;
    }
}

// ---------------------------------------------------------------------------
__global__ void zero_loss_k(float* num, float* den) { *num = 0.f; *den = 0.f; }

__global__ void loss_k(const float* __restrict__ logits, const int* __restrict__ tg,
                       float* num, float* den) {
    __shared__ float red[256];
    int row = blockIdx.x;
    const float* lr = logits + (size_t)row * VOC;
    float m = -3.0e38f;
    for (int j = threadIdx.x; j < VOC; j += 256) m = fmaxf(m, lr[j]);
    red[threadIdx.x] = m;
    __syncthreads();
    for (int off = 128; off > 0; off >>= 1) {
        if (threadIdx.x < off) red[threadIdx.x] = fmaxf(red[threadIdx.x], red[threadIdx.x + off]);
        __syncthreads();
    }
    m = red[0];
    __syncthreads();
    float s = 0.f;
    for (int j = threadIdx.x; j < VOC; j += 256) s += __expf(lr[j] - m);
    red[threadIdx.x] = s;
    __syncthreads();
    for (int off = 128; off > 0; off >>= 1) {
        if (threadIdx.x < off) red[threadIdx.x] += red[threadIdx.x + off];
        __syncthreads();
    }
    if (threadIdx.x == 0) {
        int t = tg[row];
        if (t != 0) {
            float lse = m + logf(red[0]);
            float nll = lse - lr[t];
            atomicAdd(num, nll);
            atomicAdd(den, 1.0f);
        }
    }
}

__global__ void final_loss_k(const float* num, const float* den, float* out) {
    out[0] = *num / fmaxf(*den, 1.0f);
}

// ---------------------------------------------------------------------------
extern "C" void kernel_launch(void* const* d_in, const int* in_sizes, int n_in,
                              void* d_out, int out_size) {
    const int*   idx     = (const int*)d_in[0];
    const int*   targets = (const int*)d_in[1];
    const float* wte     = (const float*)d_in[2];
    const float* wpe     = (const float*)d_in[3];
    const float* ln1_g   = (const float*)d_in[4];
    const float* ln1_b   = (const float*)d_in[5];
    const float* attn_w  = (const float*)d_in[6];
    const float* attn_b  = (const float*)d_in[7];
    const float* proj_w  = (const float*)d_in[8];
    const float* proj_b  = (const float*)d_in[9];
    const float* ln2_g   = (const float*)d_in[10];
    const float* ln2_b   = (const float*)d_in[11];
    const float* fc_w    = (const float*)d_in[12];
    const float* fc_b    = (const float*)d_in[13];
    const float* fc2_w   = (const float*)d_in[14];
    const float* fc2_b   = (const float*)d_in[15];
    const float* lnf_g   = (const float*)d_in[16];
    const float* lnf_b   = (const float*)d_in[17];
    float* out = (float*)d_out;

    float *x, *h, *qkv, *y, *mbuf, *pnum, *pden;
    cudaGetSymbolAddress((void**)&x, g_x);
    cudaGetSymbolAddress((void**)&h, g_h);
    cudaGetSymbolAddress((void**)&qkv, g_qkv);
    cudaGetSymbolAddress((void**)&y, g_y);
    cudaGetSymbolAddress((void**)&mbuf, g_m);
    cudaGetSymbolAddress((void**)&pnum, g_num);
    cudaGetSymbolAddress((void**)&pden, g_den);

    const size_t LOGN = (size_t)BT * VOC;
    float* out_loss = out + LOGN;
    float* out_x    = out + LOGN + 1;  // 4-byte aligned only — scalar access only!

    embed_k<<<BT, 256>>>(idx, wte, wpe, x);

    for (int l = 0; l < NLAY; l++) {
        ln_k<<<BT, 256>>>(x, ln1_g + l * CH, ln1_b + l * CH, h);
        gemm_nn_k<0, 0><<<dim3(3 * CH / 128, BT / 128), 256>>>(
            h, attn_w + (size_t)l * CH * 3 * CH, attn_b + (size_t)l * 3 * CH,
            nullptr, qkv, BT, 3 * CH, CH);
        attn_k<<<dim3(TSEQ, NH, 4), 128>>>(qkv, y);
        gemm_nn_k<0, 1><<<dim3(CH / 128, BT / 128), 256>>>(
            y, proj_w + (size_t)l * CH * CH, proj_b + (size_t)l * CH,
            x, x, BT, CH, CH);
        ln_k<<<BT, 256>>>(x, ln2_g + l * CH, ln2_b + l * CH, h);
        gemm_nn_k<1, 0><<<dim3(4 * CH / 128, BT / 128), 256>>>(
            h, fc_w + (size_t)l * CH * 4 * CH, fc_b + (size_t)l * 4 * CH,
            nullptr, mbuf, BT, 4 * CH, CH);
        gemm_nn_k<0, 1><<<dim3(CH / 128, BT / 128), 256>>>(
            mbuf, fc2_w + (size_t)l * 4 * CH * CH, fc2_b + (size_t)l * CH,
            x, x, BT, CH, 4 * CH);
    }

    // Final LN into ALIGNED scratch; lm-head reads scratch; scalar-copy to out_x.
    ln_k<<<BT, 256>>>(x, lnf_g, lnf_b, h);
    copy_k<<<(BT * CH + 255) / 256, 256>>>(h, out_x, BT * CH);
    gemm_nt_k<<<dim3(VOC / 128, BT / 128), 256>>>(h, wte, out, BT, VOC, CH);
    zero_loss_k<<<1, 1>>>(pnum, pden);
    loss_k<<<BT, 256>>>(out, targets, pnum, pden);
    final_loss_k<<<1, 1>>>(pnum, pden, out_loss);
}

// round 4
// speedup vs baseline: 1.1469x; 1.0062x over previous
#include <cuda_runtime.h>
#include <cuda_bf16.h>
#include <math.h>

// ---------------------------------------------------------------------------
// GPT-2 small forward: L=6, C=768, H=12, D=64, B=4, T=1024, V=32000
// Output layout: logits [4096*32000] | loss [1] | x_final [4096*768]
// Round 4: FFMA2 GEMMs + software-pipelined k-loop (register double buffering)
// ---------------------------------------------------------------------------

#define BT   4096
#define CH   768
#define NH   12
#define DH   64
#define TSEQ 1024
#define VOC  32000
#define NLAY 6

typedef unsigned long long ull;

// Scratch (device globals: no allocation allowed)
__device__ float g_x[BT * CH];
__device__ float g_h[BT * CH];
__device__ float g_qkv[BT * 3 * CH];
__device__ float g_y[BT * CH];
__device__ float g_m[BT * 4 * CH];
__device__ float g_num;
__device__ float g_den;

// ---------------------------------------------------------------------------
__global__ void embed_k(const int* __restrict__ idx, const float* __restrict__ wte,
                        const float* __restrict__ wpe, float* __restrict__ x) {
    int row = blockIdx.x;
    int t = row & (TSEQ - 1);
    int tok = idx[row];
    const float* a = wte + (size_t)tok * CH;
    const float* b = wpe + (size_t)t * CH;
    float* o = x + (size_t)row * CH;
    for (int c = threadIdx.x; c < CH; c += blockDim.x) o[c] = a[c] + b[c];
}

__global__ void copy_k(const float* __restrict__ src, float* __restrict__ dst, int n) {
    int i = blockIdx.x * blockDim.x + threadIdx.x;
    if (i < n) dst[i] = src[i];
}

// ---------------------------------------------------------------------------
__global__ void ln_k(const float* __restrict__ x, const float* __restrict__ g,
                     const float* __restrict__ b, float* __restrict__ o) {
    __shared__ float r1[256], r2[256];
    int row = blockIdx.x;
    const float* xr = x + (size_t)row * CH;
    float s = 0.f, s2 = 0.f;
    for (int i = threadIdx.x; i < CH; i += 256) { float v = xr[i]; s += v; s2 += v * v; }
    r1[threadIdx.x] = s; r2[threadIdx.x] = s2;
    __syncthreads();
    for (int off = 128; off > 0; off >>= 1) {
        if (threadIdx.x < off) {
            r1[threadIdx.x] += r1[threadIdx.x + off];
            r2[threadIdx.x] += r2[threadIdx.x + off];
        }
        __syncthreads();
    }
    float mean = r1[0] * (1.0f / CH);
    float var  = r2[0] * (1.0f / CH) - mean * mean;
    float rstd = rsqrtf(var + 1e-5f);
    float* orow = o + (size_t)row * CH;
    for (int i = threadIdx.x; i < CH; i += 256)
        orow[i] = (xr[i] - mean) * rstd * g[i] + b[i];
}

// ---------------------------------------------------------------------------
// FFMA2 helpers
__device__ __forceinline__ ull pack_dup(float a) {
    ull r;
    asm("mov.b64 %0, {%1, %1};" : "=l"(r) : "f"(a));
    return r;
}
__device__ __forceinline__ void ffma2(ull& acc, ull a, ull b) {
    asm("fma.rn.f32x2 %0, %1, %2, %0;" : "+l"(acc) : "l"(a), "l"(b));
}
__device__ __forceinline__ float lo32(ull v) { return __uint_as_float((unsigned)v); }
__device__ __forceinline__ float hi32(ull v) { return __uint_as_float((unsigned)(v >> 32)); }

// ---------------------------------------------------------------------------
// Tiled fp32 GEMM (FFMA2, pipelined): C = act(A@B + bias) (+res)
// Tile 128x128x16, 256 threads, 8x8/thread. A 16B-aligned, K%16==0, M,N%128==0.
template <int ACT, int RES>
__global__ __launch_bounds__(256, 2)
void gemm_nn_k(const float* __restrict__ A, const float* __restrict__ B,
               const float* __restrict__ bias, const float* __restrict__ res,
               float* __restrict__ Cmat, int M, int N, int K) {
    __shared__ __align__(16) float As[16][132];
    __shared__ __align__(16) float Bs[16][132];
    int tid = threadIdx.x;
    int tx = tid & 15, ty = tid >> 4;
    int row0 = blockIdx.y * 128, col0 = blockIdx.x * 128;
    ull acc[8][4] = {};
    const float* Ab = A + (size_t)row0 * K;

    // per-thread load coords
    int am0 = tid >> 2,          akq0 = (tid & 3) * 4;
    int am1 = (tid + 256) >> 2,  akq1 = ((tid + 256) & 3) * 4;
    int bkk0 = tid >> 5,         bnq0 = (tid & 31) * 4;
    int bkk1 = (tid + 256) >> 5, bnq1 = ((tid + 256) & 31) * 4;

    float4 pa0, pa1, pb0, pb1;
    // prologue: slab 0
    pa0 = *reinterpret_cast<const float4*>(&Ab[(size_t)am0 * K + akq0]);
    pa1 = *reinterpret_cast<const float4*>(&Ab[(size_t)am1 * K + akq1]);
    pb0 = *reinterpret_cast<const float4*>(&B[(size_t)bkk0 * N + col0 + bnq0]);
    pb1 = *reinterpret_cast<const float4*>(&B[(size_t)bkk1 * N + col0 + bnq1]);
    As[akq0 + 0][am0] = pa0.x; As[akq0 + 1][am0] = pa0.y;
    As[akq0 + 2][am0] = pa0.z; As[akq0 + 3][am0] = pa0.w;
    As[akq1 + 0][am1] = pa1.x; As[akq1 + 1][am1] = pa1.y;
    As[akq1 + 2][am1] = pa1.z; As[akq1 + 3][am1] = pa1.w;
    *reinterpret_cast<float4*>(&Bs[bkk0][bnq0]) = pb0;
    *reinterpret_cast<float4*>(&Bs[bkk1][bnq1]) = pb1;
    __syncthreads();

    int nS = K >> 4;
    for (int s = 0; s < nS; s++) {
        bool more = (s + 1) < nS;
        int k0n = (s + 1) << 4;
        if (more) {  // prefetch next slab into registers
            pa0 = *reinterpret_cast<const float4*>(&Ab[(size_t)am0 * K + k0n + akq0]);
            pa1 = *reinterpret_cast<const float4*>(&Ab[(size_t)am1 * K + k0n + akq1]);
            pb0 = *reinterpret_cast<const float4*>(&B[(size_t)(k0n + bkk0) * N + col0 + bnq0]);
            pb1 = *reinterpret_cast<const float4*>(&B[(size_t)(k0n + bkk1) * N + col0 + bnq1]);
        }
#pragma unroll
        for (int kk = 0; kk < 16; kk++) {
            float4 a0 = *reinterpret_cast<const float4*>(&As[kk][ty * 8]);
            float4 a1 = *reinterpret_cast<const float4*>(&As[kk][ty * 8 + 4]);
            ull ap[8];
            ap[0] = pack_dup(a0.x); ap[1] = pack_dup(a0.y);
            ap[2] = pack_dup(a0.z); ap[3] = pack_dup(a0.w);
            ap[4] = pack_dup(a1.x); ap[5] = pack_dup(a1.y);
            ap[6] = pack_dup(a1.z); ap[7] = pack_dup(a1.w);
            const ull* bq = reinterpret_cast<const ull*>(&Bs[kk][tx * 8]);
            ull bp0 = bq[0], bp1 = bq[1], bp2 = bq[2], bp3 = bq[3];
#pragma unroll
            for (int i = 0; i < 8; i++) {
                ffma2(acc[i][0], ap[i], bp0);
                ffma2(acc[i][1], ap[i], bp1);
                ffma2(acc[i][2], ap[i], bp2);
                ffma2(acc[i][3], ap[i], bp3);
            }
        }
        __syncthreads();
        if (more) {
            As[akq0 + 0][am0] = pa0.x; As[akq0 + 1][am0] = pa0.y;
            As[akq0 + 2][am0] = pa0.z; As[akq0 + 3][am0] = pa0.w;
            As[akq1 + 0][am1] = pa1.x; As[akq1 + 1][am1] = pa1.y;
            As[akq1 + 2][am1] = pa1.z; As[akq1 + 3][am1] = pa1.w;
            *reinterpret_cast<float4*>(&Bs[bkk0][bnq0]) = pb0;
            *reinterpret_cast<float4*>(&Bs[bkk1][bnq1]) = pb1;
            __syncthreads();
        }
    }
#pragma unroll
    for (int i = 0; i < 8; i++) {
        int r = row0 + ty * 8 + i;
#pragma unroll
        for (int j = 0; j < 4; j++) {
            int c = col0 + tx * 8 + j * 2;
            float v0 = lo32(acc[i][j]) + bias[c];
            float v1 = hi32(acc[i][j]) + bias[c + 1];
            if (ACT == 1) {
                v0 = 0.5f * v0 * (1.0f + erff(v0 * 0.70710678118654752440f));
                v1 = 0.5f * v1 * (1.0f + erff(v1 * 0.70710678118654752440f));
            }
            if (RES == 1) {
                float2 rv = *reinterpret_cast<const float2*>(&res[(size_t)r * N + c]);
                v0 += rv.x; v1 += rv.y;
            }
            float2 ov = make_float2(v0, v1);
            *reinterpret_cast<float2*>(&Cmat[(size_t)r * N + c]) = ov;
        }
    }
}

// ---------------------------------------------------------------------------
// NT GEMM (FFMA2, pipelined): C[M,N] = A[M,K] @ W[N,K]^T (tied lm head)
__global__ __launch_bounds__(256, 2)
void gemm_nt_k(const float* __restrict__ A, const float* __restrict__ W,
               float* __restrict__ Cmat, int M, int N, int K) {
    __shared__ __align__(16) float As[16][132];
    __shared__ __align__(16) float Bs[16][132];
    int tid = threadIdx.x;
    int tx = tid & 15, ty = tid >> 4;
    int row0 = blockIdx.y * 128, col0 = blockIdx.x * 128;
    ull acc[8][4] = {};
    const float* Ab = A + (size_t)row0 * K;
    const float* Wb = W + (size_t)col0 * K;

    int am0 = tid >> 2,          akq0 = (tid & 3) * 4;
    int am1 = (tid + 256) >> 2,  akq1 = ((tid + 256) & 3) * 4;

    float4 pa0, pa1, pb0, pb1;
    pa0 = *reinterpret_cast<const float4*>(&Ab[(size_t)am0 * K + akq0]);
    pa1 = *reinterpret_cast<const float4*>(&Ab[(size_t)am1 * K + akq1]);
    pb0 = *reinterpret_cast<const float4*>(&Wb[(size_t)am0 * K + akq0]);
    pb1 = *reinterpret_cast<const float4*>(&Wb[(size_t)am1 * K + akq1]);
    As[akq0 + 0][am0] = pa0.x; As[akq0 + 1][am0] = pa0.y;
    As[akq0 + 2][am0] = pa0.z; As[akq0 + 3][am0] = pa0.w;
    As[akq1 + 0][am1] = pa1.x; As[akq1 + 1][am1] = pa1.y;
    As[akq1 + 2][am1] = pa1.z; As[akq1 + 3][am1] = pa1.w;
    Bs[akq0 + 0][am0] = pb0.x; Bs[akq0 + 1][am0] = pb0.y;
    Bs[akq0 + 2][am0] = pb0.z; Bs[akq0 + 3][am0] = pb0.w;
    Bs[akq1 + 0][am1] = pb1.x; Bs[akq1 + 1][am1] = pb1.y;
    Bs[akq1 + 2][am1] = pb1.z; Bs[akq1 + 3][am1] = pb1.w;
    __syncthreads();

    int nS = K >> 4;
    for (int s = 0; s < nS; s++) {
        bool more = (s + 1) < nS;
        int k0n = (s + 1) << 4;
        if (more) {
            pa0 = *reinterpret_cast<const float4*>(&Ab[(size_t)am0 * K + k0n + akq0]);
            pa1 = *reinterpret_cast<const float4*>(&Ab[(size_t)am1 * K + k0n + akq1]);
            pb0 = *reinterpret_cast<const float4*>(&Wb[(size_t)am0 * K + k0n + akq0]);
            pb1 = *reinterpret_cast<const float4*>(&Wb[(size_t)am1 * K + k0n + akq1]);
        }
#pragma unroll
        for (int kk = 0; kk < 16; kk++) {
            float4 a0 = *reinterpret_cast<const float4*>(&As[kk][ty * 8]);
            float4 a1 = *reinterpret_cast<const float4*>(&As[kk][ty * 8 + 4]);
            ull ap[8];
            ap[0] = pack_dup(a0.x); ap[1] = pack_dup(a0.y);
            ap[2] = pack_dup(a0.z); ap[3] = pack_dup(a0.w);
            ap[4] = pack_dup(a1.x); ap[5] = pack_dup(a1.y);
            ap[6] = pack_dup(a1.z); ap[7] = pack_dup(a1.w);
            const ull* bq = reinterpret_cast<const ull*>(&Bs[kk][tx * 8]);
            ull bp0 = bq[0], bp1 = bq[1], bp2 = bq[2], bp3 = bq[3];
#pragma unroll
            for (int i = 0; i < 8; i++) {
                ffma2(acc[i][0], ap[i], bp0);
                ffma2(acc[i][1], ap[i], bp1);
                ffma2(acc[i][2], ap[i], bp2);
                ffma2(acc[i][3], ap[i], bp3);
            }
        }
        __syncthreads();
        if (more) {
            As[akq0 + 0][am0] = pa0.x; As[akq0 + 1][am0] = pa0.y;
            As[akq0 + 2][am0] = pa0.z; As[akq0 + 3][am0] = pa0.w;
            As[akq1 + 0][am1] = pa1.x; As[akq1 + 1][am1] = pa1.y;
            As[akq1 + 2][am1] = pa1.z; As[akq1 + 3][am1] = pa1.w;
            Bs[akq0 + 0][am0] = pb0.x; Bs[akq0 + 1][am0] = pb0.y;
            Bs[akq0 + 2][am0] = pb0.z; Bs[akq0 + 3][am0] = pb0.w;
            Bs[akq1 + 0][am1] = pb1.x; Bs[akq1 + 1][am1] = pb1.y;
            Bs[akq1 + 2][am1] = pb1.z; Bs[akq1 + 3][am1] = pb1.w;
            __syncthreads();
        }
    }
#pragma unroll
    for (int i = 0; i < 8; i++) {
        int r = row0 + ty * 8 + i;
#pragma unroll
        for (int j = 0; j < 4; j++) {
            int c = col0 + tx * 8 + j * 2;
            float2 ov = make_float2(lo32(acc[i][j]), hi32(acc[i][j]));
            *reinterpret_cast<float2*>(&Cmat[(size_t)r * N + c]) = ov;
        }
    }
}

// ---------------------------------------------------------------------------
// Causal attention, one block per (t, h, b).
__global__ void attn_k(const float* __restrict__ qkv, float* __restrict__ y) {
    __shared__ float qs[DH];
    __shared__ float sc[TSEQ];
    __shared__ float red[128];
    int t = blockIdx.x, h = blockIdx.y, b = blockIdx.z;
    int tid = threadIdx.x;
    const float* base = qkv + (size_t)b * TSEQ * (3 * CH);
    if (tid < DH) qs[tid] = base[(size_t)t * (3 * CH) + h * DH + tid];
    __syncthreads();
    int nS = t + 1;
    float lmax = -3.0e38f;
    for (int s = tid; s < nS; s += 128) {
        const float* kr = base + (size_t)s * (3 * CH) + CH + h * DH;
        float d = 0.f;
#pragma unroll
        for (int i = 0; i < DH; i++) d += qs[i] * kr[i];
        d *= 0.125f;
        sc[s] = d;
        lmax = fmaxf(lmax, d);
    }
    red[tid] = lmax;
    __syncthreads();
    for (int off = 64; off > 0; off >>= 1) {
        if (tid < off) red[tid] = fmaxf(red[tid], red[tid + off]);
        __syncthreads();
    }
    float mx = red[0];
    __syncthreads();
    float lsum = 0.f;
    for (int s = tid; s < nS; s += 128) {
        float e = __expf(sc[s] - mx);
        sc[s] = e;
        lsum += e;
    }
    red[tid] = lsum;
    __syncthreads();
    for (int off = 64; off > 0; off >>= 1) {
        if (tid < off) red[tid] += red[tid + off];
        __syncthreads();
    }
    float inv = 1.0f / red[0];
    __syncthreads();
    if (tid < DH) {
        const float* vr = base + 2 * CH + h * DH + tid;
        float acc = 0.f;
        for (int s = 0; s < nS; s++) acc += sc[s] * vr[(size_t)s * (3 * CH)];
        y[((size_t)(b * TSEQ + t)) * CH + h * DH + tid] = acc * inv;
    }
}

// ---------------------------------------------------------------------------
__global__ void zero_loss_k(float* num, float* den) { *num = 0.f; *den = 0.f; }

__global__ void loss_k(const float* __restrict__ logits, const int* __restrict__ tg,
                       float* num, float* den) {
    __shared__ float red[256];
    int row = blockIdx.x;
    const float* lr = logits + (size_t)row * VOC;
    float m = -3.0e38f;
    for (int j = threadIdx.x; j < VOC; j += 256) m = fmaxf(m, lr[j]);
    red[threadIdx.x] = m;
    __syncthreads();
    for (int off = 128; off > 0; off >>= 1) {
        if (threadIdx.x < off) red[threadIdx.x] = fmaxf(red[threadIdx.x], red[threadIdx.x + off]);
        __syncthreads();
    }
    m = red[0];
    __syncthreads();
    float s = 0.f;
    for (int j = threadIdx.x; j < VOC; j += 256) s += __expf(lr[j] - m);
    red[threadIdx.x] = s;
    __syncthreads();
    for (int off = 128; off > 0; off >>= 1) {
        if (threadIdx.x < off) red[threadIdx.x] += red[threadIdx.x + off];
        __syncthreads();
    }
    if (threadIdx.x == 0) {
        int t = tg[row];
        if (t != 0) {
            float lse = m + logf(red[0]);
            float nll = lse - lr[t];
            atomicAdd(num, nll);
            atomicAdd(den, 1.0f);
        }
    }
}

__global__ void final_loss_k(const float* num, const float* den, float* out) {
    out[0] = *num / fmaxf(*den, 1.0f);
}

// ---------------------------------------------------------------------------
extern "C" void kernel_launch(void* const* d_in, const int* in_sizes, int n_in,
                              void* d_out, int out_size) {
    const int*   idx     = (const int*)d_in[0];
    const int*   targets = (const int*)d_in[1];
    const float* wte     = (const float*)d_in[2];
    const float* wpe     = (const float*)d_in[3];
    const float* ln1_g   = (const float*)d_in[4];
    const float* ln1_b   = (const float*)d_in[5];
    const float* attn_w  = (const float*)d_in[6];
    const float* attn_b  = (const float*)d_in[7];
    const float* proj_w  = (const float*)d_in[8];
    const float* proj_b  = (const float*)d_in[9];
    const float* ln2_g   = (const float*)d_in[10];
    const float* ln2_b   = (const float*)d_in[11];
    const float* fc_w    = (const float*)d_in[12];
    const float* fc_b    = (const float*)d_in[13];
    const float* fc2_w   = (const float*)d_in[14];
    const float* fc2_b   = (const float*)d_in[15];
    const float* lnf_g   = (const float*)d_in[16];
    const float* lnf_b   = (const float*)d_in[17];
    float* out = (float*)d_out;

    float *x, *h, *qkv, *y, *mbuf, *pnum, *pden;
    cudaGetSymbolAddress((void**)&x, g_x);
    cudaGetSymbolAddress((void**)&h, g_h);
    cudaGetSymbolAddress((void**)&qkv, g_qkv);
    cudaGetSymbolAddress((void**)&y, g_y);
    cudaGetSymbolAddress((void**)&mbuf, g_m);
    cudaGetSymbolAddress((void**)&pnum, g_num);
    cudaGetSymbolAddress((void**)&pden, g_den);

    const size_t LOGN = (size_t)BT * VOC;
    float* out_loss = out + LOGN;
    float* out_x    = out + LOGN + 1;  // 4B-aligned only: scalar access

    embed_k<<<BT, 256>>>(idx, wte, wpe, x);

    for (int l = 0; l < NLAY; l++) {
        ln_k<<<BT, 256>>>(x, ln1_g + l * CH, ln1_b + l * CH, h);
        gemm_nn_k<0, 0><<<dim3(3 * CH / 128, BT / 128), 256>>>(
            h, attn_w + (size_t)l * CH * 3 * CH, attn_b + (size_t)l * 3 * CH,
            nullptr, qkv, BT, 3 * CH, CH);
        attn_k<<<dim3(TSEQ, NH, 4), 128>>>(qkv, y);
        gemm_nn_k<0, 1><<<dim3(CH / 128, BT / 128), 256>>>(
            y, proj_w + (size_t)l * CH * CH, proj_b + (size_t)l * CH,
            x, x, BT, CH, CH);
        ln_k<<<BT, 256>>>(x, ln2_g + l * CH, ln2_b + l * CH, h);
        gemm_nn_k<1, 0><<<dim3(4 * CH / 128, BT / 128), 256>>>(
            h, fc_w + (size_t)l * CH * 4 * CH, fc_b + (size_t)l * 4 * CH,
            nullptr, mbuf, BT, 4 * CH, CH);
        gemm_nn_k<0, 1><<<dim3(CH / 128, BT / 128), 256>>>(
            mbuf, fc2_w + (size_t)l * 4 * CH * CH, fc2_b + (size_t)l * CH,
            x, x, BT, CH, 4 * CH);
    }

    ln_k<<<BT, 256>>>(x, lnf_g, lnf_b, h);
    copy_k<<<(BT * CH + 255) / 256, 256>>>(h, out_x, BT * CH);
    gemm_nt_k<<<dim3(VOC / 128, BT / 128), 256>>>(h, wte, out, BT, VOC, CH);
    zero_loss_k<<<1, 1>>>(pnum, pden);
    loss_k<<<BT, 256>>>(out, targets, pnum, pden);
    final_loss_k<<<1, 1>>>(pnum, pden, out_loss);
}